// round 14
// baseline (speedup 1.0000x reference)
#include <cuda_runtime.h>
#include <cuda_bf16.h>

// Problem constants
#define H      1501          // grid side (num_grid + 1)
#define PITCH  1536          // padded row pitch (floats) -> 128B-aligned rows
#define NUM_T  400           // sequential stencil steps
#define SP     0.225f        // diff * dt * num_grid^2 / x_len^2
#define DT     1e-7f

// Temporal blocking
#define TK     4             // fused steps per launch
#define NLAUNCH (NUM_T / TK) // 100
#define TO     64            // tile output side
#define TI     72            // tile input side = TO + 2*TK
#define SST    76            // smem row stride (floats), 16B-aligned quads
#define SMEM_BYTES (3 * TI * SST * 4)   // u ping, u pong, f : 65,664 B

// Static device scratch (no allocations allowed). Zero-initialized (.bss).
__device__ float g_u0buf[H * PITCH];
__device__ float g_u1buf[H * PITCH];
__device__ float g_fbuf [H * PITCH];

// ---------------------------------------------------------------------------
// Init: copy u0 (edges intact!) into padded buffer, precompute forcing = dt*a.
// ---------------------------------------------------------------------------
__global__ void init_kernel(const float* __restrict__ u0,
                            const float* __restrict__ a)
{
    int x = blockIdx.x * blockDim.x + threadIdx.x;
    int y = blockIdx.y * blockDim.y + threadIdx.y;
    if (x >= H || y >= H) return;
    g_u0buf[y * PITCH + x] = u0[y * H + x];
    g_fbuf [y * PITCH + x] = DT * a[y * H + x];
}

// ---------------------------------------------------------------------------
// Fused TK=4 diffusion steps in shared memory.
// Tile validity invariant: after step j, cells at tile-distance >= j hold the
// correct value; outputs are at distance >= TK. Border garbage (incl. the
// never-written smem rows 0/71 of the pong buffer) propagates 1 cell/step and
// cannot reach the output interior within TK steps. At global edges the
// per-step zero mask cuts the dependency chain exactly at the boundary, so
// clamped halo loads never influence outputs.
// Per-cell arithmetic identical (same op order) to the verified 1-step kernel.
// ---------------------------------------------------------------------------
__global__ void __launch_bounds__(256)
fused4_kernel(const float* __restrict__ uin,
              const float* __restrict__ f,
              float* __restrict__ uout)
{
    extern __shared__ float sm[];
    float* sA = sm;                    // TI x SST
    float* sB = sm + TI * SST;
    float* sF = sm + 2 * TI * SST;

    const int tid = threadIdx.x;
    const int gx0 = blockIdx.x * TO - TK;   // global coord of tile local (0,0)
    const int gy0 = blockIdx.y * TO - TK;

    // ---- Load u and forcing tiles (index-clamped at global borders) ----
    for (int l = tid; l < TI * (TI / 4); l += 256) {   // 72 rows x 18 quads
        int ly  = l / (TI / 4);
        int lx0 = (l % (TI / 4)) * 4;
        int gy  = gy0 + ly;
        int gyc = gy < 0 ? 0 : (gy > H - 1 ? H - 1 : gy);
        const float* ub = uin + gyc * PITCH;
        const float* fb = f   + gyc * PITCH;
        int gx = gx0 + lx0;
        float* du = sA + ly * SST + lx0;
        float* df = sF + ly * SST + lx0;
        if (gx >= 0 && gx + 3 <= H - 1) {
            *(float4*)du = *(const float4*)(ub + gx);
            *(float4*)df = *(const float4*)(fb + gx);
        } else {
            #pragma unroll
            for (int i = 0; i < 4; ++i) {
                int gxc = gx + i < 0 ? 0 : (gx + i > H - 1 ? H - 1 : gx + i);
                du[i] = ub[gxc];
                df[i] = fb[gxc];
            }
        }
    }
    __syncthreads();

    // ---- Compute mapping: 252 active threads = 18 x-quads x 14 y-groups ----
    const int q = tid % 18;            // x-quad: lx0 = 4q (covers cols 0..71)
    const int r = tid / 18;            // y-group: rows 1+5r .. 5+5r (r < 14)
    const int lx0 = q * 4;
    const int lxm = (lx0 == 0)     ? 0  : lx0 - 1;   // clamped side reads:
    const int lxp = (lx0 + 4 > 71) ? 71 : lx0 + 4;   // border cols are garbage-ok
    const int gxq = gx0 + lx0;
    const float mx0 = (gxq     <= 0 || gxq     >= H - 1) ? 0.f : 1.f;
    const float mx1 = (gxq + 1 <= 0 || gxq + 1 >= H - 1) ? 0.f : 1.f;
    const float mx2 = (gxq + 2 <= 0 || gxq + 2 >= H - 1) ? 0.f : 1.f;
    const float mx3 = (gxq + 3 <= 0 || gxq + 3 >= H - 1) ? 0.f : 1.f;

    float* cur = sA;
    float* nxt = sB;
    #pragma unroll
    for (int s = 0; s < TK; ++s) {
        if (r < 14) {
            const int y0 = 1 + r * 5;
            float4 rma = *(float4*)(cur + (y0 - 1) * SST + lx0);
            float4 rc  = *(float4*)(cur +  y0      * SST + lx0);
            #pragma unroll
            for (int j = 0; j < 5; ++j) {
                int y = y0 + j;
                float4 rpp = *(float4*)(cur + (y + 1) * SST + lx0);
                float  lm  = cur[y * SST + lxm];
                float  rt  = cur[y * SST + lxp];
                float4 fv  = *(float4*)(sF + y * SST + lx0);
                int    gy  = gy0 + y;
                float  my  = (gy <= 0 || gy >= H - 1) ? 0.f : 1.f;
                float4 o;
                o.x = mx0 * my * (fmaf(SP, lm   + rc.y + rma.x + rpp.x - 4.0f * rc.x, rc.x) + fv.x);
                o.y = mx1 * my * (fmaf(SP, rc.x + rc.z + rma.y + rpp.y - 4.0f * rc.y, rc.y) + fv.y);
                o.z = mx2 * my * (fmaf(SP, rc.y + rc.w + rma.z + rpp.z - 4.0f * rc.z, rc.z) + fv.z);
                o.w = mx3 * my * (fmaf(SP, rc.z + rt   + rma.w + rpp.w - 4.0f * rc.w, rc.w) + fv.w);
                *(float4*)(nxt + y * SST + lx0) = o;
                rma = rc;
                rc  = rpp;
            }
        }
        __syncthreads();
        float* t = cur; cur = nxt; nxt = t;
    }

    // ---- Write 64x64 interior (local [TK, TK+TO) both dims) ----
    for (int l = tid; l < TO * (TO / 4); l += 256) {   // 64 rows x 16 quads
        int ly = l / (TO / 4);
        int lx = TK + (l % (TO / 4)) * 4;
        int y  = TK + ly;
        int gx = gx0 + lx;            // = blockIdx.x*64 + ...  (>= 0)
        int gy = gy0 + y;             // = blockIdx.y*64 + ly   (>= 0)
        if (gy < H) {
            if (gx + 3 < H) {
                *(float4*)(uout + gy * PITCH + gx) = *(float4*)(cur + y * SST + lx);
            } else {
                #pragma unroll
                for (int i = 0; i < 4; ++i)
                    if (gx + i < H) uout[gy * PITCH + gx + i] = cur[y * SST + lx + i];
            }
        }
    }
}

// ---------------------------------------------------------------------------
// De-pad: copy padded result into contiguous d_out [H, H]
// ---------------------------------------------------------------------------
__global__ void copy_out_kernel(const float* __restrict__ ubuf,
                                float* __restrict__ out)
{
    int x = blockIdx.x * blockDim.x + threadIdx.x;
    int y = blockIdx.y * blockDim.y + threadIdx.y;
    if (x >= H || y >= H) return;
    out[y * H + x] = ubuf[y * PITCH + x];
}

extern "C" void kernel_launch(void* const* d_in, const int* in_sizes, int n_in,
                              void* d_out, int out_size)
{
    const float* u0 = (const float*)d_in[0];
    const float* a  = (const float*)d_in[1];
    float* out      = (float*)d_out;

    float* p_u0 = nullptr;
    float* p_u1 = nullptr;
    float* p_f  = nullptr;
    cudaGetSymbolAddress((void**)&p_u0, g_u0buf);
    cudaGetSymbolAddress((void**)&p_u1, g_u1buf);
    cudaGetSymbolAddress((void**)&p_f,  g_fbuf);

    // Opt-in to >48KB dynamic smem (attribute set; not a stream op, capture-safe)
    cudaFuncSetAttribute(fused4_kernel,
                         cudaFuncAttributeMaxDynamicSharedMemorySize, SMEM_BYTES);

    {
        dim3 block(128, 2);
        dim3 grid((H + 127) / 128, (H + 1) / 2);
        init_kernel<<<grid, block>>>(u0, a);
    }

    // 24 x 24 tiles of 64x64 outputs; 100 launches of 4 fused steps each.
    dim3 fgrid((H + TO - 1) / TO, (H + TO - 1) / TO);   // 24 x 24 = 576 blocks

    float* bufs[2] = { p_u0, p_u1 };
    for (int t = 0; t < NLAUNCH; ++t) {
        float* uin  = bufs[t & 1];
        float* uout = bufs[(t + 1) & 1];
        fused4_kernel<<<fgrid, 256, SMEM_BYTES>>>(uin, p_f, uout);
    }

    {
        dim3 block(128, 2);
        dim3 grid((H + 127) / 128, (H + 1) / 2);
        copy_out_kernel<<<grid, block>>>(bufs[NLAUNCH & 1], out);
    }
}

// round 15
// speedup vs baseline: 1.4681x; 1.4681x over previous
#include <cuda_runtime.h>
#include <cuda_bf16.h>

// Problem constants
#define H      1501          // grid side (num_grid + 1)
#define PITCH  1536          // padded row pitch (floats) -> 128B-aligned rows
#define NUM_T  400           // sequential stencil steps
#define SP     0.225f        // diff * dt * num_grid^2 / x_len^2
#define DT     1e-7f

// Temporal blocking
#define TK     4             // fused steps per launch
#define NLAUNCH (NUM_T / TK) // 100
#define TO     64            // tile output side
#define TI     72            // tile input side = TO + 2*TK
#define SST    76            // smem row stride (floats), 16B-aligned quads
#define SMEM_BYTES (2 * TI * SST * 4)   // u ping + u pong only: 43,776 B

// Static device scratch (no allocations allowed). Zero-initialized (.bss).
__device__ float g_u0buf[H * PITCH];
__device__ float g_u1buf[H * PITCH];
__device__ float g_fbuf [H * PITCH];

// ---------------------------------------------------------------------------
// Init: copy u0 (edges intact!) into padded buffer, precompute forcing = dt*a.
// ---------------------------------------------------------------------------
__global__ void init_kernel(const float* __restrict__ u0,
                            const float* __restrict__ a)
{
    int x = blockIdx.x * blockDim.x + threadIdx.x;
    int y = blockIdx.y * blockDim.y + threadIdx.y;
    if (x >= H || y >= H) return;
    g_u0buf[y * PITCH + x] = u0[y * H + x];
    g_fbuf [y * PITCH + x] = DT * a[y * H + x];
}

// ---------------------------------------------------------------------------
// Fused TK=4 diffusion steps. u ping-pong in smem; forcing held in REGISTERS
// (each thread computes the same 20 cells each step -> 5 float4 of f loaded
// from global once, reused all 4 steps). smem = 43.8KB -> 4 blocks/SM ->
// 592 resident slots >= 576 blocks -> single wave.
// Validity invariant: outputs at tile-distance >= TK; border garbage
// propagates 1 cell/step and cannot reach them. Global-edge cells are zeroed
// by the mask every step, cutting the dependency chain exactly as the
// reference does. Per-cell FP op order identical to the verified kernels.
// ---------------------------------------------------------------------------
__global__ void __launch_bounds__(256, 4)
fused4_kernel(const float* __restrict__ uin,
              const float* __restrict__ f,
              float* __restrict__ uout)
{
    extern __shared__ float sm[];
    float* sA = sm;                    // TI x SST
    float* sB = sm + TI * SST;

    const int tid = threadIdx.x;
    const int gx0 = blockIdx.x * TO - TK;   // global coord of tile local (0,0)
    const int gy0 = blockIdx.y * TO - TK;

    // ---- Compute mapping: 252 active threads = 18 x-quads x 14 y-groups ----
    const int q = tid % 18;            // x-quad: lx0 = 4q (covers cols 0..71)
    const int r = tid / 18;            // y-group: rows 1+5r .. 5+5r (r < 14)
    const int lx0 = q * 4;
    const int lxm = (lx0 == 0)     ? 0  : lx0 - 1;   // clamped side reads:
    const int lxp = (lx0 + 4 > 71) ? 71 : lx0 + 4;   // border cols garbage-ok
    const int gxq = gx0 + lx0;
    const int y0c = 1 + r * 5;
    const float mx0 = (gxq     <= 0 || gxq     >= H - 1) ? 0.f : 1.f;
    const float mx1 = (gxq + 1 <= 0 || gxq + 1 >= H - 1) ? 0.f : 1.f;
    const float mx2 = (gxq + 2 <= 0 || gxq + 2 >= H - 1) ? 0.f : 1.f;
    const float mx3 = (gxq + 3 <= 0 || gxq + 3 >= H - 1) ? 0.f : 1.f;

    // ---- Forcing for this thread's 20 cells: registers, loaded once ----
    // Masked cells multiply f by 0, so clamped-address garbage is harmless.
    float4 fq[5];
    if (r < 14) {
        int xb = gxq < 0 ? 0 : (gxq > H - 1 ? H - 1 : gxq);  // 16B-aligned
        #pragma unroll
        for (int j = 0; j < 5; ++j) {
            int gy  = gy0 + y0c + j;
            int gyc = gy < 0 ? 0 : (gy > H - 1 ? H - 1 : gy);
            fq[j] = *(const float4*)(f + gyc * PITCH + xb);
        }
    }

    // ---- Load u tile into smem (index-clamped at global borders) ----
    for (int l = tid; l < TI * (TI / 4); l += 256) {   // 72 rows x 18 quads
        int ly  = l / (TI / 4);
        int lxq = (l % (TI / 4)) * 4;
        int gy  = gy0 + ly;
        int gyc = gy < 0 ? 0 : (gy > H - 1 ? H - 1 : gy);
        const float* ub = uin + gyc * PITCH;
        int gx = gx0 + lxq;
        float* du = sA + ly * SST + lxq;
        if (gx >= 0 && gx + 3 <= H - 1) {
            *(float4*)du = *(const float4*)(ub + gx);
        } else {
            #pragma unroll
            for (int i = 0; i < 4; ++i) {
                int gxc = gx + i < 0 ? 0 : (gx + i > H - 1 ? H - 1 : gx + i);
                du[i] = ub[gxc];
            }
        }
    }
    __syncthreads();

    float* cur = sA;
    float* nxt = sB;
    #pragma unroll
    for (int s = 0; s < TK; ++s) {
        if (r < 14) {
            float4 rma = *(float4*)(cur + (y0c - 1) * SST + lx0);
            float4 rc  = *(float4*)(cur +  y0c      * SST + lx0);
            #pragma unroll
            for (int j = 0; j < 5; ++j) {
                int y = y0c + j;
                float4 rpp = *(float4*)(cur + (y + 1) * SST + lx0);
                float  lm  = cur[y * SST + lxm];
                float  rt  = cur[y * SST + lxp];
                int    gy  = gy0 + y;
                float  my  = (gy <= 0 || gy >= H - 1) ? 0.f : 1.f;
                float4 o;
                o.x = mx0 * my * (fmaf(SP, lm   + rc.y + rma.x + rpp.x - 4.0f * rc.x, rc.x) + fq[j].x);
                o.y = mx1 * my * (fmaf(SP, rc.x + rc.z + rma.y + rpp.y - 4.0f * rc.y, rc.y) + fq[j].y);
                o.z = mx2 * my * (fmaf(SP, rc.y + rc.w + rma.z + rpp.z - 4.0f * rc.z, rc.z) + fq[j].z);
                o.w = mx3 * my * (fmaf(SP, rc.z + rt   + rma.w + rpp.w - 4.0f * rc.w, rc.w) + fq[j].w);
                *(float4*)(nxt + y * SST + lx0) = o;
                rma = rc;
                rc  = rpp;
            }
        }
        __syncthreads();
        float* t = cur; cur = nxt; nxt = t;
    }

    // ---- Write 64x64 interior (local [TK, TK+TO) both dims) ----
    for (int l = tid; l < TO * (TO / 4); l += 256) {   // 64 rows x 16 quads
        int ly = l / (TO / 4);
        int lx = TK + (l % (TO / 4)) * 4;
        int y  = TK + ly;
        int gx = gx0 + lx;            // >= 0
        int gy = gy0 + y;             // >= 0
        if (gy < H) {
            if (gx + 3 < H) {
                *(float4*)(uout + gy * PITCH + gx) = *(float4*)(cur + y * SST + lx);
            } else {
                #pragma unroll
                for (int i = 0; i < 4; ++i)
                    if (gx + i < H) uout[gy * PITCH + gx + i] = cur[y * SST + lx + i];
            }
        }
    }
}

// ---------------------------------------------------------------------------
// De-pad: copy padded result into contiguous d_out [H, H]
// ---------------------------------------------------------------------------
__global__ void copy_out_kernel(const float* __restrict__ ubuf,
                                float* __restrict__ out)
{
    int x = blockIdx.x * blockDim.x + threadIdx.x;
    int y = blockIdx.y * blockDim.y + threadIdx.y;
    if (x >= H || y >= H) return;
    out[y * H + x] = ubuf[y * PITCH + x];
}

extern "C" void kernel_launch(void* const* d_in, const int* in_sizes, int n_in,
                              void* d_out, int out_size)
{
    const float* u0 = (const float*)d_in[0];
    const float* a  = (const float*)d_in[1];
    float* out      = (float*)d_out;

    float* p_u0 = nullptr;
    float* p_u1 = nullptr;
    float* p_f  = nullptr;
    cudaGetSymbolAddress((void**)&p_u0, g_u0buf);
    cudaGetSymbolAddress((void**)&p_u1, g_u1buf);
    cudaGetSymbolAddress((void**)&p_f,  g_fbuf);

    {
        dim3 block(128, 2);
        dim3 grid((H + 127) / 128, (H + 1) / 2);
        init_kernel<<<grid, block>>>(u0, a);
    }

    // 24 x 24 tiles of 64x64 outputs; 100 launches of 4 fused steps each.
    // 43.8KB smem -> 4 blocks/SM -> 592 slots >= 576 blocks: single wave.
    dim3 fgrid((H + TO - 1) / TO, (H + TO - 1) / TO);   // 24 x 24 = 576 blocks

    float* bufs[2] = { p_u0, p_u1 };
    for (int t = 0; t < NLAUNCH; ++t) {
        float* uin  = bufs[t & 1];
        float* uout = bufs[(t + 1) & 1];
        fused4_kernel<<<fgrid, 256, SMEM_BYTES>>>(uin, p_f, uout);
    }

    {
        dim3 block(128, 2);
        dim3 grid((H + 127) / 128, (H + 1) / 2);
        copy_out_kernel<<<grid, block>>>(bufs[NLAUNCH & 1], out);
    }
}